// round 2
// baseline (speedup 1.0000x reference)
#include <cuda_runtime.h>
#include <cuda_bf16.h>

// ---------------- problem constants (dataset-fixed) ----------------
#define B_    32
#define H_    32
#define KVH_  8
#define G_    4
#define D_    128
#define SW_   4096
#define HID_  4096
#define QKVD_ 6144
#define POS_  2047          // current_pos (dataset constant)
#define L_    2048          // min(current_pos+1, SW)
#define CH_   64            // keys per attention chunk
#define NCH_  32            // L / CH
#define NHEAD_ 1024         // B * H
#define NBKV_  256          // B * KVH

// ---------------- scratch (no allocations allowed) ----------------
__device__ __align__(16) float g_part[8 * B_ * QKVD_];        // split-K partials (max of both GEMMs)
__device__ __align__(16) float g_xqkv[B_ * QKVD_];            // qkv projection
__device__ __align__(16) float g_q[B_ * H_ * D_];             // rotated+scaled q, [b][h][d]
__device__ __align__(16) float g_knew[B_ * KVH_ * D_];        // rotated new k
__device__ __align__(16) float g_vnew[B_ * KVH_ * D_];        // new v
__device__ __align__(16) float g_attout[B_ * HID_];           // attention output [b][h*D+d]
__device__ __align__(16) float g_pml[NCH_ * NHEAD_ * 2];      // per-chunk (m, l)
__device__ __align__(16) float g_po [NCH_ * NHEAD_ * D_];     // per-chunk sum e*v

// ====================================================================
// Split-K GEMM partials: Y_part[s][m][j] = sum_{k in chunk s} X[m][k]*W[k][j]
// M=32, K=4096 (8 splits of 512). Block = 128 threads, 128 cols/block,
// 1 col/thread, 32 row-accumulators. X tile staged in smem (broadcast reads).
// ====================================================================
__global__ void gemm_part(const float* __restrict__ Xin,
                          const float* __restrict__ W,
                          int N, int use_attout)
{
    const float* __restrict__ X = use_attout ? g_attout : Xin;
    __shared__ float xs[32][33];
    const int t  = threadIdx.x;
    const int j  = blockIdx.x * 128 + t;
    const int k0 = blockIdx.y * 512;

    float acc[32];
#pragma unroll
    for (int m = 0; m < 32; m++) acc[m] = 0.f;

    for (int kt = 0; kt < 512; kt += 32) {
        // stage X tile [32 rows][32 k]
#pragma unroll
        for (int i = 0; i < 2; i++) {
            int slot = t + 128 * i;          // 0..255 float4 slots
            int m  = slot >> 3;
            int q4 = slot & 7;
            const float4 v = *(const float4*)&X[m * HID_ + k0 + kt + q4 * 4];
            xs[m][q4 * 4 + 0] = v.x;
            xs[m][q4 * 4 + 1] = v.y;
            xs[m][q4 * 4 + 2] = v.z;
            xs[m][q4 * 4 + 3] = v.w;
        }
        __syncthreads();

        const float* wp = &W[(size_t)(k0 + kt) * N + j];
#pragma unroll 8
        for (int kk = 0; kk < 32; kk++) {
            float w = wp[(size_t)kk * N];
#pragma unroll
            for (int m = 0; m < 32; m++)
                acc[m] = fmaf(xs[m][kk], w, acc[m]);
        }
        __syncthreads();
    }

    float* op = g_part + ((size_t)blockIdx.y * 32) * N + j;
#pragma unroll
    for (int m = 0; m < 32; m++) op[(size_t)m * N] = acc[m];
}

// ---------------- split-K reduction (8 splits) ----------------
__global__ void reduce_part(float* __restrict__ outp, int total, int to_xqkv)
{
    float* o = to_xqkv ? g_xqkv : outp;
    int i = blockIdx.x * 256 + threadIdx.x;
    float a = 0.f;
#pragma unroll
    for (int s = 0; s < 8; s++) a += g_part[(size_t)s * total + i];
    o[i] = a;
}

// ====================================================================
// RoPE: q_rot = q @ rot (scaled by D^-1/2), k_rot = k @ rot, v copied.
// Blocks 0..1023: q head (b,h). Blocks 1024..1279: k/v head (b,kvh).
// rot (64KB) stays L2-resident; reads coalesced across threads.
// ====================================================================
__global__ void rope_kernel(const float* __restrict__ rot)
{
    __shared__ float xr[128];
    const int t   = threadIdx.x;
    const int blk = blockIdx.x;

    if (blk < 1024) {
        int b = blk >> 5, h = blk & 31;
        xr[t] = g_xqkv[b * QKVD_ + h * 128 + t];
        __syncthreads();
        float acc = 0.f;
#pragma unroll 8
        for (int d = 0; d < 128; d++)
            acc = fmaf(xr[d], rot[d * 128 + t], acc);
        g_q[blk * 128 + t] = acc * 0.08838834764831845f;   // D^-0.5
    } else {
        int kv = blk - 1024;
        int b = kv >> 3, kvh = kv & 7;
        xr[t] = g_xqkv[b * QKVD_ + 4096 + kvh * 128 + t];          // k slice
        g_vnew[kv * 128 + t] = g_xqkv[b * QKVD_ + 5120 + kvh * 128 + t]; // v slice
        __syncthreads();
        float acc = 0.f;
#pragma unroll 8
        for (int d = 0; d < 128; d++)
            acc = fmaf(xr[d], rot[d * 128 + t], acc);
        g_knew[kv * 128 + t] = acc;
    }
}

// ====================================================================
// Flash-decode attention, one (b,kvh,chunk) per block, G=4 q heads shared.
// K tile -> smem (stride 33 float4: conflict-free at structural 4-phase),
// scores (thread = (g,p), full 128-d dot), per-head partial softmax,
// V tile reuses the same smem buffer, then sum e*v.
// Position POS_ is substituted with the freshly computed k/v (cache is
// never written).
// ====================================================================
__global__ void attn_chunk(const float* __restrict__ cache_k,
                           const float* __restrict__ cache_v)
{
    __shared__ float4 kv[64 * 33];
    __shared__ float4 qs[4][32];
    __shared__ float  ss[4][64];
    __shared__ float  probs[4][64];
    __shared__ float4 pvpart[256];

    const int t   = threadIdx.x;       // 0..255
    const int bkv = blockIdx.x;        // b*8 + kvh
    const int c   = blockIdx.y;        // chunk
    const int p0  = c * CH_;

    // load 4 q heads (g_q index (b*32 + kvh*4 + g) == bkv*4 + g)
    if (t < 128) {
        int g = t >> 5, dq = t & 31;
        qs[g][dq] = *(const float4*)&g_q[(bkv * 4 + g) * 128 + dq * 4];
    }

    // load K chunk: 64 rows x 32 float4
#pragma unroll
    for (int i = 0; i < 8; i++) {
        int slot = t + 256 * i;               // 0..2047
        int p = slot >> 5, dq = slot & 31;
        int gp = p0 + p;
        const float* src = (gp == POS_)
            ? (g_knew + bkv * D_)
            : (cache_k + ((size_t)bkv * SW_ + gp) * D_);
        kv[p * 33 + dq] = *(const float4*)&src[dq * 4];
    }
    __syncthreads();

    // scores: thread = (g = t>>6, p = t&63), full dot over 128 d
    {
        int g = t >> 6, p = t & 63;
        const float4* kp = &kv[p * 33];
        const float4* qp = qs[g];
        float a = 0.f;
#pragma unroll 8
        for (int dq = 0; dq < 32; dq++) {
            float4 k4 = kp[dq], q4 = qp[dq];
            a = fmaf(k4.x, q4.x, a);
            a = fmaf(k4.y, q4.y, a);
            a = fmaf(k4.z, q4.z, a);
            a = fmaf(k4.w, q4.w, a);
        }
        ss[g][p] = a;
    }
    __syncthreads();

    // partial softmax: warp g handles head g (64 scores, 2/lane)
    const int warp = t >> 5, lane = t & 31;
    if (warp < 4) {
        float s0 = ss[warp][lane], s1 = ss[warp][lane + 32];
        float m = fmaxf(s0, s1);
#pragma unroll
        for (int o = 16; o > 0; o >>= 1)
            m = fmaxf(m, __shfl_xor_sync(0xffffffffu, m, o));
        float e0 = __expf(s0 - m), e1 = __expf(s1 - m);
        probs[warp][lane]      = e0;
        probs[warp][lane + 32] = e1;
        float l = e0 + e1;
#pragma unroll
        for (int o = 16; o > 0; o >>= 1)
            l += __shfl_xor_sync(0xffffffffu, l, o);
        if (lane == 0) {
            int head = bkv * 4 + warp;
            g_pml[(c * NHEAD_ + head) * 2 + 0] = m;
            g_pml[(c * NHEAD_ + head) * 2 + 1] = l;
        }
    }
    __syncthreads();

    // load V chunk into the same buffer
#pragma unroll
    for (int i = 0; i < 8; i++) {
        int slot = t + 256 * i;
        int p = slot >> 5, dq = slot & 31;
        int gp = p0 + p;
        const float* src = (gp == POS_)
            ? (g_vnew + bkv * D_)
            : (cache_v + ((size_t)bkv * SW_ + gp) * D_);
        kv[p * 33 + dq] = *(const float4*)&src[dq * 4];
    }
    __syncthreads();

    // pv: thread = (ph = t>>7, g = (t>>5)&3, dq = t&31), 32 p each
    {
        int dq = t & 31, g = (t >> 5) & 3, ph = t >> 7;
        float4 a = make_float4(0.f, 0.f, 0.f, 0.f);
        const float* pr = probs[g];
#pragma unroll 8
        for (int pp = 0; pp < 32; pp++) {
            int p = ph * 32 + pp;
            float w = pr[p];
            float4 v4 = kv[p * 33 + dq];
            a.x = fmaf(w, v4.x, a.x);
            a.y = fmaf(w, v4.y, a.y);
            a.z = fmaf(w, v4.z, a.z);
            a.w = fmaf(w, v4.w, a.w);
        }
        pvpart[t] = a;
    }
    __syncthreads();

    if (t < 128) {
        float4 a = pvpart[t], b4 = pvpart[t + 128];
        a.x += b4.x; a.y += b4.y; a.z += b4.z; a.w += b4.w;
        int g = t >> 5, dq = t & 31;
        int head = bkv * 4 + g;
        *(float4*)&g_po[((size_t)c * NHEAD_ + head) * D_ + dq * 4] = a;
    }
}

// ---------------- combine per-chunk softmax partials ----------------
__global__ void combine_kernel()
{
    const int head = blockIdx.x;   // 0..1023 == b*32 + h
    const int t    = threadIdx.x;  // d = 0..127

    float M = -1e30f;
#pragma unroll
    for (int c = 0; c < NCH_; c++)
        M = fmaxf(M, g_pml[(c * NHEAD_ + head) * 2]);

    float denom = 0.f, acc = 0.f;
    for (int c = 0; c < NCH_; c++) {
        float m = g_pml[(c * NHEAD_ + head) * 2 + 0];
        float l = g_pml[(c * NHEAD_ + head) * 2 + 1];
        float w = __expf(m - M);
        denom += w * l;
        acc = fmaf(w, g_po[((size_t)c * NHEAD_ + head) * D_ + t], acc);
    }
    // head = b*32 + h  ->  attout[b*4096 + h*128 + d] = head*128 + d
    g_attout[head * 128 + t] = acc / denom;
}

// ====================================================================
extern "C" void kernel_launch(void* const* d_in, const int* in_sizes, int n_in,
                              void* d_out, int out_size)
{
    const float* x    = (const float*)d_in[0];   // [1,1,32,4096]
    const float* wqkv = (const float*)d_in[1];   // [4096,6144]
    const float* wo   = (const float*)d_in[2];   // [4096,4096]
    const float* rot  = (const float*)d_in[3];   // [128,128]
    const float* ck   = (const float*)d_in[4];   // [32,8,4096,128]
    const float* cv   = (const float*)d_in[5];   // [32,8,4096,128]
    float* out = (float*)d_out;                  // [1,1,32,4096] fp32

    // 1) QKV projection (split-K) + reduce
    gemm_part<<<dim3(48, 8), 128>>>(x, wqkv, QKVD_, 0);
    reduce_part<<<768, 256>>>(nullptr, B_ * QKVD_, 1);

    // 2) RoPE rotate q/k (+ scale q), copy v
    rope_kernel<<<1280, 128>>>(rot);

    // 3) flash-decode attention over 32 chunks of 64 keys
    attn_chunk<<<dim3(NBKV_, NCH_), 256>>>(ck, cv);
    combine_kernel<<<NHEAD_, 128>>>();

    // 4) output projection (split-K) + reduce into d_out
    gemm_part<<<dim3(32, 8), 128>>>(nullptr, wo, HID_, 1);
    reduce_part<<<512, 256>>>(out, B_ * HID_, 0);
}

// round 3
// speedup vs baseline: 1.5910x; 1.5910x over previous
#include <cuda_runtime.h>
#include <cuda_bf16.h>

// ---------------- problem constants (dataset-fixed) ----------------
#define B_    32
#define H_    32
#define KVH_  8
#define G_    4
#define D_    128
#define SW_   4096
#define HID_  4096
#define QKVD_ 6144
#define POS_  2047          // current_pos (dataset constant)
#define L_    2048          // min(current_pos+1, SW)
#define CH_   64            // keys per attention chunk
#define NCH_  32            // L / CH
#define NHEAD_ 1024         // B * H
#define NBKV_  256          // B * KVH
#define SPLITS_ 16
#define KC_     (HID_ / SPLITS_)   // 256

typedef unsigned long long u64;

// ---------------- scratch (no allocations allowed) ----------------
__device__ __align__(16) float g_part[SPLITS_ * B_ * QKVD_];  // split-K partials
__device__ __align__(16) float g_xqkv[B_ * QKVD_];
__device__ __align__(16) float g_q[B_ * H_ * D_];
__device__ __align__(16) float g_knew[B_ * KVH_ * D_];
__device__ __align__(16) float g_vnew[B_ * KVH_ * D_];
__device__ __align__(16) float g_attout[B_ * HID_];
__device__ __align__(16) float g_pml[NCH_ * NHEAD_ * 2];
__device__ __align__(16) float g_po [NCH_ * NHEAD_ * D_];

// ---------------- f32x2 helpers ----------------
__device__ __forceinline__ u64 pack2(float lo, float hi) {
    u64 r; asm("mov.b64 %0, {%1, %2};" : "=l"(r) : "f"(lo), "f"(hi)); return r;
}
__device__ __forceinline__ void unpack2(u64 v, float& lo, float& hi) {
    asm("mov.b64 {%0, %1}, %2;" : "=f"(lo), "=f"(hi) : "l"(v));
}
__device__ __forceinline__ u64 fma2(u64 a, u64 b, u64 c) {
    u64 d; asm("fma.rn.f32x2 %0, %1, %2, %3;" : "=l"(d) : "l"(a), "l"(b), "l"(c)); return d;
}

// ====================================================================
// Split-K GEMM partials with packed f32x2 math.
// M=32 rows, split-K chunks of 256. Block = 128 threads, 256 cols/block
// (2 adjacent cols per thread). Row pairs packed into u64 accumulators.
// X tile staged transposed in smem [kk][m]; inner-loop X reads are
// warp-broadcast LDS.64 (free bandwidth), W reads coalesced LDG.64.
// ====================================================================
__global__ void gemm_part(const float* __restrict__ Xin,
                          const float* __restrict__ W,
                          int N, int use_attout)
{
    const float* __restrict__ X = use_attout ? g_attout : Xin;
    __shared__ float xs[32][36];   // [kk][m], stride 36 floats (8B/16B aligned rows)
    const int t  = threadIdx.x;            // 0..127
    const int j  = blockIdx.x * 256 + 2 * t;
    const int k0 = blockIdx.y * KC_;

    u64 acc[16][2];
#pragma unroll
    for (int r = 0; r < 16; r++) { acc[r][0] = 0ULL; acc[r][1] = 0ULL; }

    for (int kt = 0; kt < KC_; kt += 32) {
        // stage X tile [32 m][32 k] transposed -> xs[kk][m]
#pragma unroll
        for (int i = 0; i < 2; i++) {
            int slot = t + 128 * i;          // 0..255 float4 slots
            int m  = slot >> 3;
            int c4 = slot & 7;
            const float4 v = *(const float4*)&X[m * HID_ + k0 + kt + c4 * 4];
            xs[c4 * 4 + 0][m] = v.x;
            xs[c4 * 4 + 1][m] = v.y;
            xs[c4 * 4 + 2][m] = v.z;
            xs[c4 * 4 + 3][m] = v.w;
        }
        __syncthreads();

        const float* wp = &W[(size_t)(k0 + kt) * N + j];
#pragma unroll 8
        for (int kk = 0; kk < 32; kk++) {
            const float2 wv = *(const float2*)(wp + (size_t)kk * N);
            const u64 w0 = pack2(wv.x, wv.x);
            const u64 w1 = pack2(wv.y, wv.y);
            const u64* xr = (const u64*)&xs[kk][0];   // 16 row-pairs
#pragma unroll
            for (int r = 0; r < 16; r++) {
                u64 x2 = xr[r];                       // rows (2r, 2r+1)
                acc[r][0] = fma2(x2, w0, acc[r][0]);
                acc[r][1] = fma2(x2, w1, acc[r][1]);
            }
        }
        __syncthreads();
    }

    float* op = g_part + (size_t)blockIdx.y * 32 * N;
#pragma unroll
    for (int r = 0; r < 16; r++) {
        float a, b;
        unpack2(acc[r][0], a, b);
        op[(size_t)(2 * r) * N + j]         = a;
        op[(size_t)(2 * r + 1) * N + j]     = b;
        unpack2(acc[r][1], a, b);
        op[(size_t)(2 * r) * N + j + 1]     = a;
        op[(size_t)(2 * r + 1) * N + j + 1] = b;
    }
}

// ---------------- split-K reduction (16 splits) ----------------
__global__ void reduce_part(float* __restrict__ outp, int total, int to_xqkv)
{
    float* o = to_xqkv ? g_xqkv : outp;
    int i = blockIdx.x * 256 + threadIdx.x;
    float a = 0.f;
#pragma unroll
    for (int s = 0; s < SPLITS_; s++) a += g_part[(size_t)s * total + i];
    o[i] = a;
}

// ====================================================================
// RoPE: q_rot = q @ rot (scaled by D^-1/2), k_rot = k @ rot, v copied.
// ====================================================================
__global__ void rope_kernel(const float* __restrict__ rot)
{
    __shared__ float xr[128];
    const int t   = threadIdx.x;
    const int blk = blockIdx.x;

    if (blk < 1024) {
        int b = blk >> 5, h = blk & 31;
        xr[t] = g_xqkv[b * QKVD_ + h * 128 + t];
        __syncthreads();
        float acc = 0.f;
#pragma unroll 8
        for (int d = 0; d < 128; d++)
            acc = fmaf(xr[d], rot[d * 128 + t], acc);
        g_q[blk * 128 + t] = acc * 0.08838834764831845f;   // D^-0.5
    } else {
        int kv = blk - 1024;
        int b = kv >> 3, kvh = kv & 7;
        xr[t] = g_xqkv[b * QKVD_ + 4096 + kvh * 128 + t];
        g_vnew[kv * 128 + t] = g_xqkv[b * QKVD_ + 5120 + kvh * 128 + t];
        __syncthreads();
        float acc = 0.f;
#pragma unroll 8
        for (int d = 0; d < 128; d++)
            acc = fmaf(xr[d], rot[d * 128 + t], acc);
        g_knew[kv * 128 + t] = acc;
    }
}

// ====================================================================
// Flash-decode attention, one (b,kvh,chunk) per block, 256 threads.
// K and V both loaded up front into separate buffers (all DRAM latency
// overlaps). Each k/v element is read from smem ONCE and used for all
// G=4 q heads (4x less smem traffic than head-per-thread). All dot/pv
// math packed f32x2. Position POS_ substituted with fresh k/v.
// Dynamic smem layout (92160 B):
//   kbuf[64*33] f4 | vbuf[64*33] f4 | qs[4*32] f4 | pvp[8*4*32] f4 |
//   ss[4][4][64] f | sfin[4][64] f | probs[4][64] f
// ====================================================================
#define ATT_SMEM_ 92160

__global__ void attn_chunk(const float* __restrict__ cache_k,
                           const float* __restrict__ cache_v)
{
    extern __shared__ char smem_raw[];
    float4* kbuf = (float4*)smem_raw;           // 64*33
    float4* vbuf = kbuf + 64 * 33;              // 64*33
    float4* qs   = vbuf + 64 * 33;              // 4*32
    float4* pvp  = qs + 128;                    // 8*4*32
    float*  ss   = (float*)(pvp + 1024);        // [dc][g][p] = 4*4*64
    float*  sfin = ss + 1024;                   // [g][p] = 4*64
    float*  probs= sfin + 256;                  // [g][p] = 4*64

    const int t   = threadIdx.x;       // 0..255
    const int bkv = blockIdx.x;        // b*8 + kvh
    const int c   = blockIdx.y;        // chunk
    const int p0  = c * CH_;

    // q heads for this kv group: g_q head index = bkv*4 + g
    if (t < 128) {
        int g = t >> 5, dq = t & 31;
        qs[g * 32 + dq] = *(const float4*)&g_q[(bkv * 4 + g) * 128 + dq * 4];
    }

    // K chunk: 64 rows x 32 float4 (then V) — both issued before any use
#pragma unroll
    for (int i = 0; i < 8; i++) {
        int slot = t + 256 * i;               // 0..2047
        int p = slot >> 5, dq = slot & 31;
        int gp = p0 + p;
        const float* src = (gp == POS_)
            ? (g_knew + bkv * D_)
            : (cache_k + ((size_t)bkv * SW_ + gp) * D_);
        kbuf[p * 33 + dq] = *(const float4*)&src[dq * 4];
    }
#pragma unroll
    for (int i = 0; i < 8; i++) {
        int slot = t + 256 * i;
        int p = slot >> 5, dq = slot & 31;
        int gp = p0 + p;
        const float* src = (gp == POS_)
            ? (g_vnew + bkv * D_)
            : (cache_v + ((size_t)bkv * SW_ + gp) * D_);
        vbuf[p * 33 + dq] = *(const float4*)&src[dq * 4];
    }
    __syncthreads();

    // scores: thread = (p = t&63, dc = t>>6); k element read once, used
    // for all 4 heads. Packed over d pairs.
    {
        int p = t & 63, dc = t >> 6;
        const u64* kp = (const u64*)&kbuf[p * 33 + dc * 8];   // 16 u64 (32 d)
        const u64* q2 = (const u64*)qs;                       // [g*64 + d2]
        u64 a0 = 0ULL, a1 = 0ULL, a2 = 0ULL, a3 = 0ULL;
#pragma unroll
        for (int i = 0; i < 16; i++) {
            u64 k2 = kp[i];
            int qi = dc * 16 + i;
            a0 = fma2(k2, q2[qi],       a0);
            a1 = fma2(k2, q2[64 + qi],  a1);
            a2 = fma2(k2, q2[128 + qi], a2);
            a3 = fma2(k2, q2[192 + qi], a3);
        }
        float lo, hi;
        unpack2(a0, lo, hi); ss[(dc * 4 + 0) * 64 + p] = lo + hi;
        unpack2(a1, lo, hi); ss[(dc * 4 + 1) * 64 + p] = lo + hi;
        unpack2(a2, lo, hi); ss[(dc * 4 + 2) * 64 + p] = lo + hi;
        unpack2(a3, lo, hi); ss[(dc * 4 + 3) * 64 + p] = lo + hi;
    }
    __syncthreads();

    // sum the 4 d-chunks: thread = (g = t>>6, p = t&63)
    {
        int g = t >> 6, p = t & 63;
        sfin[g * 64 + p] = (ss[(0 * 4 + g) * 64 + p] + ss[(1 * 4 + g) * 64 + p])
                         + (ss[(2 * 4 + g) * 64 + p] + ss[(3 * 4 + g) * 64 + p]);
    }
    __syncthreads();

    // partial softmax: warp g (g<4) handles head g
    const int warp = t >> 5, lane = t & 31;
    if (warp < 4) {
        float s0 = sfin[warp * 64 + lane], s1 = sfin[warp * 64 + lane + 32];
        float m = fmaxf(s0, s1);
#pragma unroll
        for (int o = 16; o > 0; o >>= 1)
            m = fmaxf(m, __shfl_xor_sync(0xffffffffu, m, o));
        float e0 = __expf(s0 - m), e1 = __expf(s1 - m);
        probs[warp * 64 + lane]      = e0;
        probs[warp * 64 + lane + 32] = e1;
        float l = e0 + e1;
#pragma unroll
        for (int o = 16; o > 0; o >>= 1)
            l += __shfl_xor_sync(0xffffffffu, l, o);
        if (lane == 0) {
            int head = bkv * 4 + warp;
            g_pml[(c * NHEAD_ + head) * 2 + 0] = m;
            g_pml[(c * NHEAD_ + head) * 2 + 1] = l;
        }
    }
    __syncthreads();

    // pv: thread = (pg = t>>5, dq = t&31), 8 p each; v element read once,
    // accumulated into all 4 heads (packed f32x2).
    {
        int pg = t >> 5, dq = t & 31;
        u64 ax[4], ay[4];
#pragma unroll
        for (int g = 0; g < 4; g++) { ax[g] = 0ULL; ay[g] = 0ULL; }
#pragma unroll
        for (int pp = 0; pp < 8; pp++) {
            int p = pg * 8 + pp;
            const u64* v2 = (const u64*)&vbuf[p * 33 + dq];
            u64 va = v2[0], vb = v2[1];
#pragma unroll
            for (int g = 0; g < 4; g++) {
                float w = probs[g * 64 + p];
                u64 wd = pack2(w, w);
                ax[g] = fma2(va, wd, ax[g]);
                ay[g] = fma2(vb, wd, ay[g]);
            }
        }
#pragma unroll
        for (int g = 0; g < 4; g++) {
            float4 r;
            unpack2(ax[g], r.x, r.y);
            unpack2(ay[g], r.z, r.w);
            pvp[(pg * 4 + g) * 32 + dq] = r;
        }
    }
    __syncthreads();

    // reduce 8 p-groups: thread = (g = t>>5, dq = t&31) for t<128
    if (t < 128) {
        int g = t >> 5, dq = t & 31;
        float4 a = make_float4(0.f, 0.f, 0.f, 0.f);
#pragma unroll
        for (int pg = 0; pg < 8; pg++) {
            float4 v = pvp[(pg * 4 + g) * 32 + dq];
            a.x += v.x; a.y += v.y; a.z += v.z; a.w += v.w;
        }
        int head = bkv * 4 + g;
        *(float4*)&g_po[((size_t)c * NHEAD_ + head) * D_ + dq * 4] = a;
    }
}

// ---------------- combine per-chunk softmax partials ----------------
__global__ void combine_kernel()
{
    const int head = blockIdx.x;   // b*32 + h
    const int t    = threadIdx.x;  // d

    float M = -1e30f;
#pragma unroll
    for (int c = 0; c < NCH_; c++)
        M = fmaxf(M, g_pml[(c * NHEAD_ + head) * 2]);

    float denom = 0.f, acc = 0.f;
    for (int c = 0; c < NCH_; c++) {
        float m = g_pml[(c * NHEAD_ + head) * 2 + 0];
        float l = g_pml[(c * NHEAD_ + head) * 2 + 1];
        float w = __expf(m - M);
        denom += w * l;
        acc = fmaf(w, g_po[((size_t)c * NHEAD_ + head) * D_ + t], acc);
    }
    g_attout[head * 128 + t] = acc / denom;
}

// ====================================================================
extern "C" void kernel_launch(void* const* d_in, const int* in_sizes, int n_in,
                              void* d_out, int out_size)
{
    const float* x    = (const float*)d_in[0];
    const float* wqkv = (const float*)d_in[1];
    const float* wo   = (const float*)d_in[2];
    const float* rot  = (const float*)d_in[3];
    const float* ck   = (const float*)d_in[4];
    const float* cv   = (const float*)d_in[5];
    float* out = (float*)d_out;

    static int smem_set = 0;
    if (!smem_set) {
        cudaFuncSetAttribute(attn_chunk,
                             cudaFuncAttributeMaxDynamicSharedMemorySize,
                             ATT_SMEM_);
        smem_set = 1;
    }

    // 1) QKV projection (split-K 16) + reduce
    gemm_part<<<dim3(24, SPLITS_), 128>>>(x, wqkv, QKVD_, 0);
    reduce_part<<<768, 256>>>(nullptr, B_ * QKVD_, 1);

    // 2) RoPE
    rope_kernel<<<1280, 128>>>(rot);

    // 3) flash-decode attention
    attn_chunk<<<dim3(NBKV_, NCH_), 256, ATT_SMEM_>>>(ck, cv);
    combine_kernel<<<NHEAD_, 128>>>();

    // 4) output projection + reduce into d_out
    gemm_part<<<dim3(16, SPLITS_), 128>>>(nullptr, wo, HID_, 1);
    reduce_part<<<512, 256>>>(out, B_ * HID_, 0);
}